// round 14
// baseline (speedup 1.0000x reference)
#include <cuda_runtime.h>
#include <cuda_bf16.h>

#define TT 1024
#define BB 4096
#define TOTAL4 (BB * TT / 4)        // 1048576 float4-groups
#define NBLK 148                    // 1 CTA of 1024 threads per SM (one wave)
#define NRED 4                      // last-4 arriving blocks do the reduction
#define NEGBIG (-1.0e30f)

// ---- device scratch (static; counters self-reset each launch) ----
__device__ __align__(16) float        g_S[NBLK * 3072];   // [blk][p=3t+c]
__device__ __align__(16) unsigned int g_C[NBLK * 768];    // [blk][3*(t>>2)+c], byte=t&3
__device__ __align__(16) float        g_pS[3072];
__device__ __align__(16) int          g_pN[3072];
__device__ unsigned int          g_tick1 = 0;             // main-done tickets
__device__ volatile unsigned int g_done1 = 0;             // count of fenced slab writes
__device__ unsigned int          g_tick2 = 0;             // reducer-done tickets

// ======================= special functions (R6-exact) =======================
__device__ __forceinline__ float stirl_lg(float y) {
    float r  = __fdividef(1.0f, y);
    float L  = __logf(y);
    float r2 = r * r;
    return fmaf(y - 0.5f, L,
                fmaf(r, fmaf(r2, -2.7777778e-3f, 8.3333333e-2f), 0.91893853f - y));
}

__device__ __forceinline__ void stirl_both(float y, float& lg, float& ps) {
    float r  = __fdividef(1.0f, y);
    float L  = __logf(y);
    float r2 = r * r;
    lg = fmaf(y - 0.5f, L,
              fmaf(r, fmaf(r2, -2.7777778e-3f, 8.3333333e-2f), 0.91893853f - y));
    ps = fmaf(-r2, fmaf(-r2, 8.3333333e-3f, 8.3333333e-2f), fmaf(-0.5f, r, L));
}

__device__ __forceinline__ float elem_kl(float l0, float l1, float tw, float tcv) {
    float pw  = __fdividef(1.0f, 1.0f + __expf(-l0));
    float pcs = __fdividef(1.0f, 1.0f + __expf(-l1));
    float pc  = fmaf(pcs, 1023.0f, 5.0f);

    float sp = tcv + 2.0f;
    float sq = pc + 2.0f;
    float ta = fmaf(tcv, tw, 1.0f);
    float tb = sp - ta;
    float pa = fmaf(pc, pw, 1.0f);
    float pb = sq - pa;

    float uta = ta * (ta + 3.0f), Pta = uta * (uta + 2.0f);
    float utb = tb * (tb + 3.0f), Ptb = utb * (utb + 2.0f);
    float upa = pa * (pa + 3.0f), Ppa = upa * (upa + 2.0f);
    float upb = pb * (pb + 3.0f), Ppb = upb * (upb + 2.0f);

    float lgta, psta; stirl_both(ta + 4.0f, lgta, psta);
    float lgtb, pstb; stirl_both(tb + 4.0f, lgtb, pstb);
    float lgsp, pssp; stirl_both(sp,        lgsp, pssp);
    float lgpa = stirl_lg(pa + 4.0f);
    float lgpb = stirl_lg(pb + 4.0f);
    float lgsq = stirl_lg(sq);

    float da = ta - pa, db = tb - pb;
    float Aa  = fmaf(2.0f, uta, 2.0f) * fmaf(2.0f, ta, 3.0f);
    float Ab  = fmaf(2.0f, utb, 2.0f) * fmaf(2.0f, tb, 3.0f);
    float Ptt = Pta * Ptb;
    float corr = __fdividef(fmaf(da * Aa, Ptb, db * Ab * Pta), Ptt);

    float logdiff = __logf(Ptt) - __logf(Ppa * Ppb);

    return (lgpa + lgpb + lgsp) - (lgta + lgtb + lgsq) + logdiff
         + da * psta + db * pstb + (sq - sp) * pssp - corr;
}

// ======================= single kernel: main KL pass + tail reduction =======================
// Phase 1 is byte-identical R6. Non-reducer blocks exit; last-4 blocks reduce.
__global__ void __launch_bounds__(1024)
main_kernel(const float* __restrict__ logits, const float* __restrict__ tgt,
            float* __restrict__ out) {
    const int tid = threadIdx.x;
    const int q = tid >> 8, r = tid & 255;
    const float4* tg4 = reinterpret_cast<const float4*>(tgt);
    const float4* lg4 = reinterpret_cast<const float4*>(logits);

    float s[4][3];
#pragma unroll
    for (int j = 0; j < 4; j++) { s[j][0] = 0.0f; s[j][1] = 0.0f; s[j][2] = 0.0f; }
    unsigned int cn[3] = {0u, 0u, 0u};

#pragma unroll 1
    for (int g = blockIdx.x * 1024 + tid; g < TOTAL4; g += NBLK * 1024) {
        float4 a = tg4[g * 3 + 0];
        float4 b = tg4[g * 3 + 1];
        float4 c = tg4[g * 3 + 2];
        float4 d = lg4[g * 2 + 0];
        float4 e = lg4[g * 2 + 1];
        float tv[12] = {a.x, a.y, a.z, a.w, b.x, b.y, b.z, b.w, c.x, c.y, c.z, c.w};
        float lv[8]  = {d.x, d.y, d.z, d.w, e.x, e.y, e.z, e.w};
#pragma unroll
        for (int j = 0; j < 4; j++) {
            float x0 = tv[3 * j], x1 = tv[3 * j + 1], x2 = tv[3 * j + 2];
            bool  m  = (x2 > NEGBIG);
            float tw = m ? x0 : 0.5f;
            float tc = m ? x1 : 5.0f;
            int   dx = m ? (int)x2 : -1;
            float kl = elem_kl(lv[2 * j], lv[2 * j + 1], tw, tc);
            s[j][0] += (dx == 0) ? kl : 0.0f;
            s[j][1] += (dx == 1) ? kl : 0.0f;
            s[j][2] += (dx == 2) ? kl : 0.0f;
            cn[0] += (dx == 0) ? (1u << (8 * j)) : 0u;
            cn[1] += (dx == 1) ? (1u << (8 * j)) : 0u;
            cn[2] += (dx == 2) ? (1u << (8 * j)) : 0u;
        }
    }

    // 4-phase fixed-order quarter fold in smem (thread-quarters share t-sets)
    __shared__ float        sh[3072];
    __shared__ unsigned int shc[768];
    if (q == 0) {
#pragma unroll
        for (int j = 0; j < 4; j++)
#pragma unroll
            for (int c = 0; c < 3; c++) sh[12 * r + 3 * j + c] = s[j][c];
#pragma unroll
        for (int c = 0; c < 3; c++) shc[3 * r + c] = cn[c];
    }
    __syncthreads();
#pragma unroll
    for (int qq = 1; qq < 4; qq++) {
        if (q == qq) {
#pragma unroll
            for (int j = 0; j < 4; j++)
#pragma unroll
                for (int c = 0; c < 3; c++) sh[12 * r + 3 * j + c] += s[j][c];
#pragma unroll
            for (int c = 0; c < 3; c++) shc[3 * r + c] += cn[c];
        }
        __syncthreads();
    }

    if (q == 0) {
        const float4* shv = reinterpret_cast<const float4*>(&sh[12 * r]);
        float4* so = reinterpret_cast<float4*>(&g_S[blockIdx.x * 3072 + 12 * r]);
        so[0] = shv[0]; so[1] = shv[1]; so[2] = shv[2];
        unsigned int* co = &g_C[blockIdx.x * 768 + 3 * r];
        co[0] = shc[3 * r]; co[1] = shc[3 * r + 1]; co[2] = shc[3 * r + 2];
    }

    // -------- tail: ticket; last NRED arriving blocks become reducers --------
    __syncthreads();
    __shared__ unsigned int sticket;
    if (tid == 0) {
        __threadfence();                                  // publish slab writes
        unsigned int t1 = atomicAdd(&g_tick1, 1u);
        atomicAdd((unsigned int*)&g_done1, 1u);           // fenced-write count
        sticket = t1;
    }
    __syncthreads();
    unsigned int ticket = sticket;
    if (ticket < NBLK - NRED) return;                     // non-reducers exit now
    const int quarter = (int)ticket - (NBLK - NRED);      // 0..3

    // wait until ALL blocks' slab writes are published (short spin: we're a straggler)
    if (tid == 0) { while (g_done1 != NBLK) { } }
    __syncthreads();
    __threadfence();

    // -------- reduce this quarter of p-space (fixed order -> deterministic) --------
    // S: threads 0..767 own p = quarter*768 + tid (warp-coalesced over blocks)
    if (tid < 768) {
        const int p = quarter * 768 + tid;
        float acc = 0.0f;
#pragma unroll 4
        for (int b = 0; b < NBLK; b++)
            acc += g_S[b * 3072 + p];
        g_pS[p] = acc;
    } else if (tid < 960) {
        // counts: threads 768..959 own count-word wi = quarter*192 + (tid-768)
        const int wi = quarter * 192 + (tid - 768);
        int n[4] = {0, 0, 0, 0};
        int b = 0;
#pragma unroll 1
        for (int chunk = 0; chunk < 17; chunk++) {        // 9 words/chunk: 9*28=252<=255
            unsigned int acc = 0;
#pragma unroll
            for (int i = 0; i < 9; i++) {
                if (b < NBLK) { acc += g_C[b * 768 + wi]; b++; }
            }
            n[0] += (int)(acc & 0xFFu);
            n[1] += (int)((acc >> 8) & 0xFFu);
            n[2] += (int)((acc >> 16) & 0xFFu);
            n[3] += (int)(acc >> 24);
        }
        int t4 = wi / 3, c = wi - 3 * t4;                 // byte j -> t = 4*t4+j
#pragma unroll
        for (int j = 0; j < 4; j++)
            g_pN[12 * t4 + 3 * j + c] = n[j];             // index 3t+c
    }

    __syncthreads();
    __shared__ unsigned int sticket2;
    if (tid == 0) {
        __threadfence();                                  // publish partials
        sticket2 = atomicAdd(&g_tick2, 1u);
    }
    __syncthreads();
    if (sticket2 != NRED - 1) return;                     // only the truly-last folds
    __threadfence();

    // -------- final fold: 1024 threads, one t each --------
    {
        float acc = 0.0f;
#pragma unroll
        for (int c = 0; c < 3; c++) {
            float S = g_pS[3 * tid + c];
            int   N = g_pN[3 * tid + c];
            acc += (N > 0) ? __fdividef(S, 3.0f * (float)N) : 0.0f;
        }
#pragma unroll
        for (int off = 16; off > 0; off >>= 1)
            acc += __shfl_xor_sync(0xffffffffu, acc, off);
        __shared__ float ws[32];
        if ((tid & 31) == 0) ws[tid >> 5] = acc;
        __syncthreads();
        if (tid == 0) {
            float tot = 0.0f;
#pragma unroll
            for (int i = 0; i < 32; i++) tot += ws[i];
            out[0] = tot * (1.0f / (float)TT);
            // reset counters for next graph replay
            g_tick1 = 0;
            g_done1 = 0;
            g_tick2 = 0;
        }
    }
}

// ======================= launch =======================
extern "C" void kernel_launch(void* const* d_in, const int* in_sizes, int n_in,
                              void* d_out, int out_size) {
    const float* logits;
    const float* targets;
    if (in_sizes[0] == BB * TT * 2) {          // robust to metadata ordering
        logits  = (const float*)d_in[0];
        targets = (const float*)d_in[1];
    } else {
        logits  = (const float*)d_in[1];
        targets = (const float*)d_in[0];
    }
    float* out = (float*)d_out;

    main_kernel<<<NBLK, 1024>>>(logits, targets, out);
}

// round 16
// speedup vs baseline: 1.6884x; 1.6884x over previous
#include <cuda_runtime.h>
#include <cuda_bf16.h>
#include <cstdint>

#define TT 1024
#define BB 4096
#define TOTAL4 (BB * TT / 4)        // 1048576 float4-groups
#define NBLK 148                    // 1 CTA of 1024 threads per SM
#define GSTRIDE (NBLK * 1024)       // 151552
#define ITERS 7                     // ceil(TOTAL4 / GSTRIDE)
#define BUFU 5376                   // float4s per buffer: 3072 tgt + 2304 padded logits
#define RBLKS 120                   // 96 S-blocks + 24 count-blocks
#define NEGBIG (-1.0e30f)

// ---- device scratch (static; counter self-resets each launch) ----
__device__ __align__(16) float        g_S[NBLK * 3072];   // [blk][p=3t+c]
__device__ __align__(16) unsigned int g_C[NBLK * 768];    // [blk][3*(t>>2)+c], byte=t&3
__device__ __align__(16) float        g_pS[3072];
__device__ __align__(16) int          g_pN[3072];
__device__ unsigned int g_rcnt;

// ======================= special functions (R6-exact) =======================
__device__ __forceinline__ float stirl_lg(float y) {
    float r  = __fdividef(1.0f, y);
    float L  = __logf(y);
    float r2 = r * r;
    return fmaf(y - 0.5f, L,
                fmaf(r, fmaf(r2, -2.7777778e-3f, 8.3333333e-2f), 0.91893853f - y));
}

__device__ __forceinline__ void stirl_both(float y, float& lg, float& ps) {
    float r  = __fdividef(1.0f, y);
    float L  = __logf(y);
    float r2 = r * r;
    lg = fmaf(y - 0.5f, L,
              fmaf(r, fmaf(r2, -2.7777778e-3f, 8.3333333e-2f), 0.91893853f - y));
    ps = fmaf(-r2, fmaf(-r2, 8.3333333e-3f, 8.3333333e-2f), fmaf(-0.5f, r, L));
}

__device__ __forceinline__ float elem_kl(float l0, float l1, float tw, float tcv) {
    float pw  = __fdividef(1.0f, 1.0f + __expf(-l0));
    float pcs = __fdividef(1.0f, 1.0f + __expf(-l1));
    float pc  = fmaf(pcs, 1023.0f, 5.0f);

    float sp = tcv + 2.0f;
    float sq = pc + 2.0f;
    float ta = fmaf(tcv, tw, 1.0f);
    float tb = sp - ta;
    float pa = fmaf(pc, pw, 1.0f);
    float pb = sq - pa;

    float uta = ta * (ta + 3.0f), Pta = uta * (uta + 2.0f);
    float utb = tb * (tb + 3.0f), Ptb = utb * (utb + 2.0f);
    float upa = pa * (pa + 3.0f), Ppa = upa * (upa + 2.0f);
    float upb = pb * (pb + 3.0f), Ppb = upb * (upb + 2.0f);

    float lgta, psta; stirl_both(ta + 4.0f, lgta, psta);
    float lgtb, pstb; stirl_both(tb + 4.0f, lgtb, pstb);
    float lgsp, pssp; stirl_both(sp,        lgsp, pssp);
    float lgpa = stirl_lg(pa + 4.0f);
    float lgpb = stirl_lg(pb + 4.0f);
    float lgsq = stirl_lg(sq);

    float da = ta - pa, db = tb - pb;
    float Aa  = fmaf(2.0f, uta, 2.0f) * fmaf(2.0f, ta, 3.0f);
    float Ab  = fmaf(2.0f, utb, 2.0f) * fmaf(2.0f, tb, 3.0f);
    float Ptt = Pta * Ptb;
    float corr = __fdividef(fmaf(da * Aa, Ptb, db * Ab * Pta), Ptt);

    float logdiff = __logf(Ptt) - __logf(Ppa * Ppb);

    return (lgpa + lgpb + lgsp) - (lgta + lgtb + lgsq) + logdiff
         + da * psta + db * pstb + (sq - sp) * pssp - corr;
}

// ======================= cp.async helpers =======================
__device__ __forceinline__ void cp16(unsigned int saddr, const void* gptr) {
    asm volatile("cp.async.cg.shared.global [%0], [%1], 16;"
                 :: "r"(saddr), "l"(gptr) : "memory");
}

// Stage one block-tile (targets 3072 x 16B linear; logits 2048 x 16B padded k+(k>>3)).
__device__ __forceinline__ void stage_tile(const uint4* __restrict__ tg4,
                                           const uint4* __restrict__ lg4,
                                           int it, int buf, int tid,
                                           float4* sbuf) {
    const int W0 = it * GSTRIDE + blockIdx.x * 1024;
    const int b3 = W0 * 3, b2 = W0 * 2;
    const int lim3 = TOTAL4 * 3 - b3;
    const int lim2 = TOTAL4 * 2 - b2;
    unsigned int sb = (unsigned int)__cvta_generic_to_shared(sbuf + buf * BUFU);
#pragma unroll
    for (int k0 = 0; k0 < 3; k0++) {
        int k = tid + k0 * 1024;
        if (k < lim3) cp16(sb + (unsigned int)k * 16u, tg4 + b3 + k);
    }
#pragma unroll
    for (int k0 = 0; k0 < 2; k0++) {
        int k = tid + k0 * 1024;
        if (k < lim2) cp16(sb + (unsigned int)(3072 + k + (k >> 3)) * 16u, lg4 + b2 + k);
    }
    asm volatile("cp.async.commit_group;" ::: "memory");
}

// ======================= kernel 1: main KL pass (cp.async pipelined) =======================
__global__ void __launch_bounds__(1024)
main_kernel(const float* __restrict__ logits, const float* __restrict__ tgt) {
    extern __shared__ float4 sbuf[];                     // 2 * BUFU float4
    const int tid = threadIdx.x;
    const int q = tid >> 8, r = tid & 255;
    const uint4* tg4 = reinterpret_cast<const uint4*>(tgt);
    const uint4* lg4 = reinterpret_cast<const uint4*>(logits);

    float s[4][3];
#pragma unroll
    for (int j = 0; j < 4; j++) { s[j][0] = 0.0f; s[j][1] = 0.0f; s[j][2] = 0.0f; }
    unsigned int cn[3] = {0u, 0u, 0u};

    stage_tile(tg4, lg4, 0, 0, tid, sbuf);               // prologue

#pragma unroll 1
    for (int it = 0; it < ITERS; it++) {
        if (it + 1 < ITERS) {
            stage_tile(tg4, lg4, it + 1, (it + 1) & 1, tid, sbuf);
            asm volatile("cp.async.wait_group 1;" ::: "memory");
        } else {
            asm volatile("cp.async.wait_group 0;" ::: "memory");
        }
        __syncthreads();

        const int g = it * GSTRIDE + blockIdx.x * 1024 + tid;
        if (g < TOTAL4) {
            const float4* bp = sbuf + (it & 1) * BUFU;
            float4 a = bp[3 * tid];
            float4 b = bp[3 * tid + 1];
            float4 c = bp[3 * tid + 2];
            int j0 = 2 * tid, j1 = 2 * tid + 1;
            float4 d = bp[3072 + j0 + (j0 >> 3)];
            float4 e = bp[3072 + j1 + (j1 >> 3)];
            float tv[12] = {a.x, a.y, a.z, a.w, b.x, b.y, b.z, b.w, c.x, c.y, c.z, c.w};
            float lv[8]  = {d.x, d.y, d.z, d.w, e.x, e.y, e.z, e.w};
#pragma unroll
            for (int j = 0; j < 4; j++) {
                float x0 = tv[3 * j], x1 = tv[3 * j + 1], x2 = tv[3 * j + 2];
                bool  m  = (x2 > NEGBIG);
                float tw = m ? x0 : 0.5f;
                float tc = m ? x1 : 5.0f;
                int   dx = m ? (int)x2 : -1;
                float kl = elem_kl(lv[2 * j], lv[2 * j + 1], tw, tc);
                s[j][0] += (dx == 0) ? kl : 0.0f;
                s[j][1] += (dx == 1) ? kl : 0.0f;
                s[j][2] += (dx == 2) ? kl : 0.0f;
                cn[0] += (dx == 0) ? (1u << (8 * j)) : 0u;
                cn[1] += (dx == 1) ? (1u << (8 * j)) : 0u;
                cn[2] += (dx == 2) ? (1u << (8 * j)) : 0u;
            }
        }
        __syncthreads();                                 // buffer reuse safety
    }

    // 4-phase fixed-order quarter fold in smem (thread-quarters share t-sets)
    __shared__ float        sh[3072];
    __shared__ unsigned int shc[768];
    if (q == 0) {
#pragma unroll
        for (int j = 0; j < 4; j++)
#pragma unroll
            for (int c = 0; c < 3; c++) sh[12 * r + 3 * j + c] = s[j][c];
#pragma unroll
        for (int c = 0; c < 3; c++) shc[3 * r + c] = cn[c];
    }
    __syncthreads();
#pragma unroll
    for (int qq = 1; qq < 4; qq++) {
        if (q == qq) {
#pragma unroll
            for (int j = 0; j < 4; j++)
#pragma unroll
                for (int c = 0; c < 3; c++) sh[12 * r + 3 * j + c] += s[j][c];
#pragma unroll
            for (int c = 0; c < 3; c++) shc[3 * r + c] += cn[c];
        }
        __syncthreads();
    }

    if (q == 0) {
        const float4* shv = reinterpret_cast<const float4*>(&sh[12 * r]);
        float4* so = reinterpret_cast<float4*>(&g_S[blockIdx.x * 3072 + 12 * r]);
        so[0] = shv[0]; so[1] = shv[1]; so[2] = shv[2];
        unsigned int* co = &g_C[blockIdx.x * 768 + 3 * r];
        co[0] = shc[3 * r]; co[1] = shc[3 * r + 1]; co[2] = shc[3 * r + 2];
    }
}

// ======================= kernel 2: reduce + finalize (R6-exact) =======================
__global__ void __launch_bounds__(256)
reduce_kernel(float* __restrict__ out) {
    const int tid = threadIdx.x;
    const int w = tid >> 5, l = tid & 31;
    __shared__ float sS[8][32];
    __shared__ int   sN[8][32][4];

    if (blockIdx.x < 96) {
        const int p = blockIdx.x * 32 + l;
        float acc = 0.0f;
#pragma unroll
        for (int b = w; b < NBLK; b += 8)
            acc += g_S[b * 3072 + p];
        sS[w][l] = acc;
        __syncthreads();
        if (w == 0) {
            float ssum = 0.0f;
#pragma unroll
            for (int i = 0; i < 8; i++) ssum += sS[i][l];
            g_pS[p] = ssum;
        }
    } else {
        const int wi = (blockIdx.x - 96) * 32 + l;
        int n[4] = {0, 0, 0, 0};
        int b = w;
#pragma unroll
        for (int chunk = 0; chunk < 3; chunk++) {
            unsigned int acc = 0;
#pragma unroll
            for (int i = 0; i < 9; i++) {
                if (b < NBLK) { acc += g_C[b * 768 + wi]; b += 8; }
            }
            n[0] += (int)(acc & 0xFFu);
            n[1] += (int)((acc >> 8) & 0xFFu);
            n[2] += (int)((acc >> 16) & 0xFFu);
            n[3] += (int)(acc >> 24);
        }
#pragma unroll
        for (int j = 0; j < 4; j++) sN[w][l][j] = n[j];
        __syncthreads();
        if (w == 0) {
            int t4 = wi / 3, c = wi - 3 * t4;
#pragma unroll
            for (int j = 0; j < 4; j++) {
                int nsum = 0;
#pragma unroll
                for (int i = 0; i < 8; i++) nsum += sN[i][l][j];
                g_pN[12 * t4 + 3 * j + c] = nsum;
            }
        }
    }

    __threadfence();
    __syncthreads();
    __shared__ bool amLast;
    if (tid == 0)
        amLast = (atomicAdd(&g_rcnt, 1u) == (unsigned)(RBLKS - 1));
    __syncthreads();
    if (!amLast) return;
    __threadfence();

    const float4* ps4 = reinterpret_cast<const float4*>(&g_pS[12 * tid]);
    const int4*   pn4 = reinterpret_cast<const int4*>(&g_pN[12 * tid]);
    float acc = 0.0f;
#pragma unroll
    for (int k = 0; k < 3; k++) {
        float4 S = ps4[k];
        int4   N = pn4[k];
        acc += (N.x > 0) ? __fdividef(S.x, 3.0f * (float)N.x) : 0.0f;
        acc += (N.y > 0) ? __fdividef(S.y, 3.0f * (float)N.y) : 0.0f;
        acc += (N.z > 0) ? __fdividef(S.z, 3.0f * (float)N.z) : 0.0f;
        acc += (N.w > 0) ? __fdividef(S.w, 3.0f * (float)N.w) : 0.0f;
    }

#pragma unroll
    for (int off = 16; off > 0; off >>= 1)
        acc += __shfl_xor_sync(0xffffffffu, acc, off);
    __shared__ float ws[8];
    if ((tid & 31) == 0) ws[tid >> 5] = acc;
    __syncthreads();
    if (tid == 0) {
        float tot = 0.0f;
#pragma unroll
        for (int i = 0; i < 8; i++) tot += ws[i];
        out[0] = tot * (1.0f / (float)TT);
        g_rcnt = 0;
    }
}

// ======================= launch =======================
extern "C" void kernel_launch(void* const* d_in, const int* in_sizes, int n_in,
                              void* d_out, int out_size) {
    const float* logits;
    const float* targets;
    if (in_sizes[0] == BB * TT * 2) {
        logits  = (const float*)d_in[0];
        targets = (const float*)d_in[1];
    } else {
        logits  = (const float*)d_in[1];
        targets = (const float*)d_in[0];
    }
    float* out = (float*)d_out;

    const int smem = 2 * BUFU * 16;                      // 172032 B dynamic
    cudaFuncSetAttribute(main_kernel,
                         cudaFuncAttributeMaxDynamicSharedMemorySize, smem);
    main_kernel<<<NBLK, 1024, smem>>>(logits, targets);
    reduce_kernel<<<RBLKS, 256>>>(out);
}

// round 17
// speedup vs baseline: 1.9802x; 1.1728x over previous
#include <cuda_runtime.h>
#include <cuda_bf16.h>

#define TT 1024
#define BB 4096
#define TOTAL4 (BB * TT / 4)        // 1048576 float4-groups
#define NBLK 148                    // 1 CTA of 1024 threads per SM
#define GSTRIDE (NBLK * 1024)
#define RBLKS 120                   // 96 S-blocks + 24 count-blocks
#define NEGBIG (-1.0e30f)

// ---- device scratch (static; counter self-resets each launch) ----
__device__ __align__(16) float        g_S[NBLK * 3072];   // [blk][p=3t+c]
__device__ __align__(16) unsigned int g_C[NBLK * 768];    // [blk][3*(t>>2)+c], byte=t&3
__device__ __align__(16) float        g_pS[3072];
__device__ __align__(16) int          g_pN[3072];
__device__ unsigned int g_rcnt;

// ======================= special functions (R6-exact) =======================
__device__ __forceinline__ float stirl_lg(float y) {
    float r  = __fdividef(1.0f, y);
    float L  = __logf(y);
    float r2 = r * r;
    return fmaf(y - 0.5f, L,
                fmaf(r, fmaf(r2, -2.7777778e-3f, 8.3333333e-2f), 0.91893853f - y));
}

__device__ __forceinline__ void stirl_both(float y, float& lg, float& ps) {
    float r  = __fdividef(1.0f, y);
    float L  = __logf(y);
    float r2 = r * r;
    lg = fmaf(y - 0.5f, L,
              fmaf(r, fmaf(r2, -2.7777778e-3f, 8.3333333e-2f), 0.91893853f - y));
    ps = fmaf(-r2, fmaf(-r2, 8.3333333e-3f, 8.3333333e-2f), fmaf(-0.5f, r, L));
}

__device__ __forceinline__ float elem_kl(float l0, float l1, float tw, float tcv) {
    float pw  = __fdividef(1.0f, 1.0f + __expf(-l0));
    float pcs = __fdividef(1.0f, 1.0f + __expf(-l1));
    float pc  = fmaf(pcs, 1023.0f, 5.0f);

    float sp = tcv + 2.0f;
    float sq = pc + 2.0f;
    float ta = fmaf(tcv, tw, 1.0f);
    float tb = sp - ta;
    float pa = fmaf(pc, pw, 1.0f);
    float pb = sq - pa;

    float uta = ta * (ta + 3.0f), Pta = uta * (uta + 2.0f);
    float utb = tb * (tb + 3.0f), Ptb = utb * (utb + 2.0f);
    float upa = pa * (pa + 3.0f), Ppa = upa * (upa + 2.0f);
    float upb = pb * (pb + 3.0f), Ppb = upb * (upb + 2.0f);

    float lgta, psta; stirl_both(ta + 4.0f, lgta, psta);
    float lgtb, pstb; stirl_both(tb + 4.0f, lgtb, pstb);
    float lgsp, pssp; stirl_both(sp,        lgsp, pssp);
    float lgpa = stirl_lg(pa + 4.0f);
    float lgpb = stirl_lg(pb + 4.0f);
    float lgsq = stirl_lg(sq);

    float da = ta - pa, db = tb - pb;
    float Aa  = fmaf(2.0f, uta, 2.0f) * fmaf(2.0f, ta, 3.0f);
    float Ab  = fmaf(2.0f, utb, 2.0f) * fmaf(2.0f, tb, 3.0f);
    float Ptt = Pta * Ptb;
    float corr = __fdividef(fmaf(da * Aa, Ptb, db * Ab * Pta), Ptt);

    float logdiff = __logf(Ptt) - __logf(Ppa * Ppb);

    return (lgpa + lgpb + lgsp) - (lgta + lgtb + lgsq) + logdiff
         + da * psta + db * pstb + (sq - sp) * pssp - corr;
}

// ======================= kernel 1: main KL pass =======================
// R6 schedule + warp->slice permutation pi(w) = (w>>2)|((w&3)<<3) so each SMSP
// covers all 8 t-windows, + warp-uniform padding skip (now load-balanced).
__global__ void __launch_bounds__(1024)
main_kernel(const float* __restrict__ logits, const float* __restrict__ tgt) {
    const int tid = threadIdx.x;
    const int w = tid >> 5, lane = tid & 31;
    const int pw  = (w >> 2) | ((w & 3) << 3);           // permuted warp slot
    const int pos = (pw << 5) | lane;                    // tile position 0..1023
    const int q = pos >> 8, r = pos & 255;               // quarter / t-base index
    const float4* tg4 = reinterpret_cast<const float4*>(tgt);
    const float4* lg4 = reinterpret_cast<const float4*>(logits);

    float s[4][3];
#pragma unroll
    for (int j = 0; j < 4; j++) { s[j][0] = 0.0f; s[j][1] = 0.0f; s[j][2] = 0.0f; }
    unsigned int cn[3] = {0u, 0u, 0u};

#pragma unroll 1
    for (int g = blockIdx.x * 1024 + pos; g < TOTAL4; g += GSTRIDE) {
        // unconditional front-batched loads (keep MLP high)
        float4 a = tg4[g * 3 + 0];
        float4 b = tg4[g * 3 + 1];
        float4 c = tg4[g * 3 + 2];
        float4 d = lg4[g * 2 + 0];
        float4 e = lg4[g * 2 + 1];
        // class entries for j=0..3: a.z, b.y, c.x, c.w — -inf iff padded
        float mx = fmaxf(fmaxf(a.z, b.y), fmaxf(c.x, c.w));
        if (__any_sync(0xffffffffu, mx > NEGBIG)) {      // warp-uniform skip
            float tv[12] = {a.x, a.y, a.z, a.w, b.x, b.y, b.z, b.w, c.x, c.y, c.z, c.w};
            float lv[8]  = {d.x, d.y, d.z, d.w, e.x, e.y, e.z, e.w};
#pragma unroll
            for (int j = 0; j < 4; j++) {
                float x0 = tv[3 * j], x1 = tv[3 * j + 1], x2 = tv[3 * j + 2];
                bool  m  = (x2 > NEGBIG);
                float tw = m ? x0 : 0.5f;
                float tc = m ? x1 : 5.0f;
                int   dx = m ? (int)x2 : -1;
                float kl = elem_kl(lv[2 * j], lv[2 * j + 1], tw, tc);
                s[j][0] += (dx == 0) ? kl : 0.0f;
                s[j][1] += (dx == 1) ? kl : 0.0f;
                s[j][2] += (dx == 2) ? kl : 0.0f;
                cn[0] += (dx == 0) ? (1u << (8 * j)) : 0u;
                cn[1] += (dx == 1) ? (1u << (8 * j)) : 0u;
                cn[2] += (dx == 2) ? (1u << (8 * j)) : 0u;
            }
        }
    }

    // 4-phase fixed-order quarter fold in smem (phase order by q -> same sum
    // order as R6 regardless of the warp permutation: bit-identical result)
    __shared__ float        sh[3072];
    __shared__ unsigned int shc[768];
    if (q == 0) {
#pragma unroll
        for (int j = 0; j < 4; j++)
#pragma unroll
            for (int c = 0; c < 3; c++) sh[12 * r + 3 * j + c] = s[j][c];
#pragma unroll
        for (int c = 0; c < 3; c++) shc[3 * r + c] = cn[c];
    }
    __syncthreads();
#pragma unroll
    for (int qq = 1; qq < 4; qq++) {
        if (q == qq) {
#pragma unroll
            for (int j = 0; j < 4; j++)
#pragma unroll
                for (int c = 0; c < 3; c++) sh[12 * r + 3 * j + c] += s[j][c];
#pragma unroll
            for (int c = 0; c < 3; c++) shc[3 * r + c] += cn[c];
        }
        __syncthreads();
    }

    if (q == 0) {
        const float4* shv = reinterpret_cast<const float4*>(&sh[12 * r]);
        float4* so = reinterpret_cast<float4*>(&g_S[blockIdx.x * 3072 + 12 * r]);
        so[0] = shv[0]; so[1] = shv[1]; so[2] = shv[2];
        unsigned int* co = &g_C[blockIdx.x * 768 + 3 * r];
        co[0] = shc[3 * r]; co[1] = shc[3 * r + 1]; co[2] = shc[3 * r + 2];
    }
}

// ======================= kernel 2: reduce + finalize (R6-exact) =======================
__global__ void __launch_bounds__(256)
reduce_kernel(float* __restrict__ out) {
    const int tid = threadIdx.x;
    const int w = tid >> 5, l = tid & 31;
    __shared__ float sS[8][32];
    __shared__ int   sN[8][32][4];

    if (blockIdx.x < 96) {
        const int p = blockIdx.x * 32 + l;
        float acc = 0.0f;
#pragma unroll
        for (int b = w; b < NBLK; b += 8)
            acc += g_S[b * 3072 + p];                    // coalesced per warp
        sS[w][l] = acc;
        __syncthreads();
        if (w == 0) {
            float ssum = 0.0f;
#pragma unroll
            for (int i = 0; i < 8; i++) ssum += sS[i][l];
            g_pS[p] = ssum;
        }
    } else {
        const int wi = (blockIdx.x - 96) * 32 + l;       // count word 0..767
        int n[4] = {0, 0, 0, 0};
        int b = w;
#pragma unroll
        for (int chunk = 0; chunk < 3; chunk++) {
            unsigned int acc = 0;
#pragma unroll
            for (int i = 0; i < 9; i++) {
                if (b < NBLK) { acc += g_C[b * 768 + wi]; b += 8; }
            }
            n[0] += (int)(acc & 0xFFu);
            n[1] += (int)((acc >> 8) & 0xFFu);
            n[2] += (int)((acc >> 16) & 0xFFu);
            n[3] += (int)(acc >> 24);
        }
#pragma unroll
        for (int j = 0; j < 4; j++) sN[w][l][j] = n[j];
        __syncthreads();
        if (w == 0) {
            int t4 = wi / 3, c = wi - 3 * t4;            // byte j -> t = 4*t4+j
#pragma unroll
            for (int j = 0; j < 4; j++) {
                int nsum = 0;
#pragma unroll
                for (int i = 0; i < 8; i++) nsum += sN[i][l][j];
                g_pN[12 * t4 + 3 * j + c] = nsum;
            }
        }
    }

    __threadfence();
    __syncthreads();
    __shared__ bool amLast;
    if (tid == 0)
        amLast = (atomicAdd(&g_rcnt, 1u) == (unsigned)(RBLKS - 1));
    __syncthreads();
    if (!amLast) return;
    __threadfence();

    // fold: thread owns t = 4*tid+j; 12 S + 12 N contiguous reads
    const float4* ps4 = reinterpret_cast<const float4*>(&g_pS[12 * tid]);
    const int4*   pn4 = reinterpret_cast<const int4*>(&g_pN[12 * tid]);
    float acc = 0.0f;
#pragma unroll
    for (int k = 0; k < 3; k++) {
        float4 S = ps4[k];
        int4   N = pn4[k];
        acc += (N.x > 0) ? __fdividef(S.x, 3.0f * (float)N.x) : 0.0f;
        acc += (N.y > 0) ? __fdividef(S.y, 3.0f * (float)N.y) : 0.0f;
        acc += (N.z > 0) ? __fdividef(S.z, 3.0f * (float)N.z) : 0.0f;
        acc += (N.w > 0) ? __fdividef(S.w, 3.0f * (float)N.w) : 0.0f;
    }

#pragma unroll
    for (int off = 16; off > 0; off >>= 1)
        acc += __shfl_xor_sync(0xffffffffu, acc, off);
    __shared__ float ws[8];
    if ((tid & 31) == 0) ws[tid >> 5] = acc;
    __syncthreads();
    if (tid == 0) {
        float tot = 0.0f;
#pragma unroll
        for (int i = 0; i < 8; i++) tot += ws[i];
        out[0] = tot * (1.0f / (float)TT);
        g_rcnt = 0;                                      // reset for next replay
    }
}

// ======================= launch =======================
extern "C" void kernel_launch(void* const* d_in, const int* in_sizes, int n_in,
                              void* d_out, int out_size) {
    const float* logits;
    const float* targets;
    if (in_sizes[0] == BB * TT * 2) {
        logits  = (const float*)d_in[0];
        targets = (const float*)d_in[1];
    } else {
        logits  = (const float*)d_in[1];
        targets = (const float*)d_in[0];
    }
    float* out = (float*)d_out;

    main_kernel<<<NBLK, 1024>>>(logits, targets);
    reduce_kernel<<<RBLKS, 256>>>(out);
}